// round 8
// baseline (speedup 1.0000x reference)
#include <cuda_runtime.h>

#define BB 4
#define NN 8
#define HH 48
#define WW 48
#define HW (HH*WW)        /* 2304 */
#define TH 6
#define SMH (TH+6)
#define SMW (WW+6)
#define OUTM_ELEMS (BB*3*HW)   /* 27648 */

// Zero the pred_img accumulation region (float4 stores).
__global__ void zero_kernel(float4* __restrict__ p)
{
    int i = blockIdx.x * blockDim.x + threadIdx.x;
    if (i < OUTM_ELEMS/4) p[i] = make_float4(0.f, 0.f, 0.f, 0.f);
}

// Fused rank-1 kernel-prediction apply + n-mean accumulation.
// One RGB channel t per block. The 32-channel core batch for color c+1 is
// prefetched (ping-pong registers) while color c is being computed, so the
// DRAM pipe never drains between batches.
//
// pred_img_i[b,n,t,h,w] = 0.25 * sum_s W[b,n,s,t] * S_{K(s)},  K(s)=7,5,3,1
// S_K = sum_c sum_k c1[cur+k,c,t] * sum_l c2[cur+l,c,t] * F[c, h+k-3, w+l-3]
__global__ __launch_bounds__(WW*TH, 2)
void kpn_kernel(const float* __restrict__ frames,
                const float* __restrict__ core,
                const float* __restrict__ kw,
                float* __restrict__ out_i,
                float* __restrict__ out_m)
{
    const int tile = blockIdx.x / 3;
    const int t    = blockIdx.x - tile*3;
    const int n    = blockIdx.y;
    const int b    = blockIdx.z;
    const int h0   = tile * TH;

    __shared__ float sF[4][SMH][SMW];   // 10368 B

    const int tid = threadIdx.x;

    // Cooperative load of the frames tile (zero-padded halo of 3)
    const float* fbase = frames + ((size_t)(b*NN + n)) * 4 * HW;
    for (int idx = tid; idx < 4*SMH*SMW; idx += WW*TH) {
        int c   = idx / (SMH*SMW);
        int rem = idx - c*(SMH*SMW);
        int i   = rem / SMW;
        int j   = rem - i*SMW;
        int hh  = h0 + i - 3;
        int wp  = j - 3;
        float v = 0.f;
        if ((unsigned)hh < HH && (unsigned)wp < WW)
            v = fbase[c*HW + hh*WW + wp];
        sF[c][i][j] = v;
    }

    const int w   = tid % WW;
    const int ti  = tid / WW;            // 0..TH-1
    const int h   = h0 + ti;
    const int pix = h*WW + w;

    // core channels: ch = ((q*4 + c)*3 + t), stride HW. q<16 -> c1, q>=16 -> c2.
    const float* cbase = core + (size_t)b*3072*HW + (size_t)n*384*HW
                              + (size_t)t*HW + pix;

    // kernel_weight[b][n][s][t][h][w]; hoisted so these LDGs fly with batch 0.
    const float* wbp = kw + ((size_t)(b*NN + n)) * 4 * 3 * HW + (size_t)t*HW + pix;
    float wb0 = wbp[0*3*HW], wb1 = wbp[1*3*HW], wb2 = wbp[2*3*HW], wb3 = wbp[3*3*HW];

    // Ping-pong channel batches: [parity][q]
    float c1v[2][16], c2v[2][16];

    // Prefetch batch for c = 0
    #pragma unroll
    for (int q = 0; q < 16; q++) {
        c1v[0][q] = cbase[(size_t)(((q     )*4 + 0)*3) * HW];
        c2v[0][q] = cbase[(size_t)(((16 + q)*4 + 0)*3) * HW];
    }

    __syncthreads();

    float acc0 = 0.f, acc1 = 0.f, acc2 = 0.f, acc3 = 0.f;  // K1,K3,K5,K7

    #pragma unroll
    for (int c = 0; c < 4; c++) {
        const int cur = c & 1;
        const int nxt = cur ^ 1;

        // Prefetch the next color's 32-channel batch while computing this one.
        if (c < 3) {
            #pragma unroll
            for (int q = 0; q < 16; q++) {
                c1v[nxt][q] = cbase[(size_t)(((q     )*4 + (c+1))*3) * HW];
                c2v[nxt][q] = cbase[(size_t)(((16 + q)*4 + (c+1))*3) * HW];
            }
        }

        // Walk the 7 patch rows once; each row feeds K7 always,
        // K5 for i in [1,5], K3 for i in [2,4], K1 at i==3.
        #pragma unroll
        for (int i = 0; i < 7; i++) {
            float v[7];
            #pragma unroll
            for (int l = 0; l < 7; l++)
                v[l] = sF[c][ti + i][w + l];

            // K7: cur=9, pad=0
            float rs7 = 0.f;
            #pragma unroll
            for (int l = 0; l < 7; l++)
                rs7 += c2v[cur][9 + l] * v[l];
            acc3 += c1v[cur][9 + i] * rs7;

            // K5: cur=4, pad=1 (rows 1..5)
            if (i >= 1 && i <= 5) {
                float rs5 = 0.f;
                #pragma unroll
                for (int l = 0; l < 5; l++)
                    rs5 += c2v[cur][4 + l] * v[1 + l];
                acc2 += c1v[cur][4 + (i - 1)] * rs5;
            }
            // K3: cur=1, pad=2 (rows 2..4)
            if (i >= 2 && i <= 4) {
                float rs3 = c2v[cur][1]*v[2] + c2v[cur][2]*v[3] + c2v[cur][3]*v[4];
                acc1 += c1v[cur][1 + (i - 2)] * rs3;
            }
            // K1: cur=0, pad=3 (row 3)
            if (i == 3)
                acc0 += c1v[cur][0] * (c2v[cur][0] * v[3]);
        }
    }

    // s=0 pairs with K=7 (stack order KS[::-1])
    float r = wb0 * acc3 + wb1 * acc2 + wb2 * acc1 + wb3 * acc0;

    out_i[((size_t)(b*NN + n)) * 3 * HW + (size_t)t*HW + pix] = 0.25f * r;
    atomicAdd(out_m + (size_t)b * 3 * HW + (size_t)t*HW + pix, 0.03125f * r);
}

extern "C" void kernel_launch(void* const* d_in, const int* in_sizes, int n_in,
                              void* d_out, int out_size)
{
    const float* frames = (const float*)d_in[0];
    const float* core   = (const float*)d_in[1];
    const float* kw     = (const float*)d_in[2];

    float* out   = (float*)d_out;
    float* out_i = out;                    // pred_img_i: (4,8,3,48,48) = 221184
    float* out_m = out + BB*NN*3*HW;       // pred_img:   (4,3,48,48)   =  27648

    zero_kernel<<<(OUTM_ELEMS/4 + 255)/256, 256>>>((float4*)out_m);

    dim3 grid((HH/TH)*3, NN, BB);          // 24 x 8 x 4 = 768 blocks
    kpn_kernel<<<grid, WW*TH>>>(frames, core, kw, out_i, out_m);
}

// round 9
// speedup vs baseline: 1.1552x; 1.1552x over previous
#include <cuda_runtime.h>

#define BB 4
#define NN 8
#define HH 48
#define WW 48
#define HW (HH*WW)              /* 2304 */
#define TH 6
#define SMH (TH+6)
#define SMW (WW+6)
#define BPIX (WW*TH)            /* 288 pixels per block, contiguous */
#define SF_FLOATS (4*SMH*SMW)   /* 2592 */
#define STG_FLOATS (32*BPIX)    /* 9216 floats = 36864 B per stage */
#define SMEM_BYTES ((SF_FLOATS + 2*STG_FLOATS)*4)   /* 84096 */
#define OUTM_ELEMS (BB*3*HW)    /* 27648 */

// Zero the pred_img accumulation region (float4 stores).
__global__ void zero_kernel(float4* __restrict__ p)
{
    int i = blockIdx.x * blockDim.x + threadIdx.x;
    if (i < OUTM_ELEMS/4) p[i] = make_float4(0.f, 0.f, 0.f, 0.f);
}

__device__ __forceinline__ void cp16(unsigned dst, const char* src)
{
    asm volatile("cp.async.cg.shared.global [%0], [%1], 16;"
                 :: "r"(dst), "l"(src) : "memory");
}
__device__ __forceinline__ void cp_commit()
{
    asm volatile("cp.async.commit_group;" ::: "memory");
}
__device__ __forceinline__ void cp_wait1()
{
    asm volatile("cp.async.wait_group 1;" ::: "memory");
}

// Fused rank-1 kernel-prediction apply + n-mean accumulation.
// The core stream is staged through SMEM with a cp.async double-buffered
// ring (stage = one (c,t) pair = 32 channels x 1152 B contiguous strips),
// so DRAM MLP is not bounded by the register file.
//
// pred_img_i[b,n,t,h,w] = 0.25 * sum_s W[b,n,s,t] * S_{K(s)},  K(s)=7,5,3,1
// S_K = sum_c sum_k c1[cur+k,c,t] * sum_l c2[cur+l,c,t] * F[c, h+k-3, w+l-3]
// core channel index within (b,n): ch = 12*q + 3*c + t,  q in [0,32)
__global__ __launch_bounds__(BPIX, 2)
void kpn_kernel(const float* __restrict__ frames,
                const float* __restrict__ core,
                const float* __restrict__ kw,
                float* __restrict__ out_i,
                float* __restrict__ out_m)
{
    extern __shared__ float smem[];
    float* sF   = smem;               // [4][SMH][SMW]
    float* ring = smem + SF_FLOATS;   // 2 stages x [32][BPIX]

    const int tile = blockIdx.x;
    const int n    = blockIdx.y;
    const int b    = blockIdx.z;
    const int h0   = tile * TH;
    const int tid  = threadIdx.x;

    // ---- frames tile (zero-padded halo of 3) via plain LDG ----
    const float* fbase = frames + ((size_t)(b*NN + n)) * 4 * HW;
    for (int idx = tid; idx < SF_FLOATS; idx += BPIX) {
        int c   = idx / (SMH*SMW);
        int rem = idx - c*(SMH*SMW);
        int i   = rem / SMW;
        int j   = rem - i*SMW;
        int hh  = h0 + i - 3;
        int wp  = j - 3;
        float v = 0.f;
        if ((unsigned)hh < HH && (unsigned)wp < WW)
            v = fbase[c*HW + hh*WW + wp];
        sF[idx] = v;
    }

    // ---- cp.async stage issue setup ----
    // Block pixel range is contiguous: pix0 = tile*BPIX. Stage s holds rows
    // q=0..31 (channels ch=12q+s), each row = 1152 B. 2304 16B-chunks/stage,
    // 8 per thread: chunk = k*288 + tid -> q = 4k + tid/72, col16 = tid%72.
    const char* gsrc = (const char*)(core + ((size_t)b*3072 + (size_t)n*384)*HW
                                          + (size_t)tile*BPIX);
    unsigned ring_sh = (unsigned)__cvta_generic_to_shared(ring);
    const int qb   = tid / 72;
    const int col  = tid - qb*72;
    const int cofs = col * 16;

    #define ISSUE_STAGE(S) do {                                              \
        unsigned dsb = ring_sh + (unsigned)(((S) & 1) * (STG_FLOATS*4));     \
        _Pragma("unroll")                                                    \
        for (int k = 0; k < 8; k++) {                                        \
            int q = k*4 + qb;                                                \
            cp16(dsb + (unsigned)(q*(BPIX*4) + cofs),                        \
                 gsrc + (size_t)(12*q + (S)) * (HW*4) + cofs);               \
        }                                                                    \
    } while (0)

    ISSUE_STAGE(0); cp_commit();
    ISSUE_STAGE(1); cp_commit();

    // kernel_weight[b][n][s][t][h][w] — hoisted, flies with the first stages.
    const int   pix = h0*WW + tid;      // pix = h0*48 + tid (contiguous block)
    const float* wbp = kw + ((size_t)(b*NN + n)) * 12 * HW + pix;
    float wb[4][3];
    #pragma unroll
    for (int s4 = 0; s4 < 4; s4++)
        #pragma unroll
        for (int t = 0; t < 3; t++)
            wb[s4][t] = wbp[(s4*3 + t)*HW];

    const int w  = tid % WW;
    const int ti = tid / WW;

    float acc[4][3];                    // [K-group g: 0=K1,1=K3,2=K5,3=K7][t]
    #pragma unroll
    for (int g = 0; g < 4; g++)
        #pragma unroll
        for (int t = 0; t < 3; t++) acc[g][t] = 0.f;

    #pragma unroll 1
    for (int c = 0; c < 4; c++) {
        #pragma unroll
        for (int t = 0; t < 3; t++) {
            const int s = c*3 + t;

            cp_wait1();                 // stage s complete (s+1 still flying)
            __syncthreads();            // visibility (also covers sF on s==0)

            const float* bufp = ring + (size_t)(s & 1) * STG_FLOATS;
            float c1v[16], c2v[16];
            #pragma unroll
            for (int q = 0; q < 16; q++) {
                c1v[q] = bufp[q       *BPIX + tid];
                c2v[q] = bufp[(16 + q)*BPIX + tid];
            }

            // Walk the 7 patch rows; row i feeds K7 always, K5 for 1..5,
            // K3 for 2..4, K1 at 3.
            #pragma unroll
            for (int i = 0; i < 7; i++) {
                float v[7];
                #pragma unroll
                for (int l = 0; l < 7; l++)
                    v[l] = sF[(c*SMH + ti + i)*SMW + w + l];

                float rs7 = 0.f;
                #pragma unroll
                for (int l = 0; l < 7; l++)
                    rs7 += c2v[9 + l] * v[l];
                acc[3][t] += c1v[9 + i] * rs7;

                if (i >= 1 && i <= 5) {
                    float rs5 = 0.f;
                    #pragma unroll
                    for (int l = 0; l < 5; l++)
                        rs5 += c2v[4 + l] * v[1 + l];
                    acc[2][t] += c1v[4 + (i - 1)] * rs5;
                }
                if (i >= 2 && i <= 4) {
                    float rs3 = c2v[1]*v[2] + c2v[2]*v[3] + c2v[3]*v[4];
                    acc[1][t] += c1v[1 + (i - 2)] * rs3;
                }
                if (i == 3)
                    acc[0][t] += c1v[0] * (c2v[0] * v[3]);
            }

            __syncthreads();            // all reads of buf(s&1) done
            if (s < 10) ISSUE_STAGE(s + 2);
            cp_commit();                // exactly one group per stage
        }
    }

    // s=0 pairs with K=7 (stack order KS[::-1])
    float* ob = out_i + ((size_t)(b*NN + n)) * 3 * HW + pix;
    float* om = out_m + (size_t)b * 3 * HW + pix;
    #pragma unroll
    for (int t = 0; t < 3; t++) {
        float r = wb[0][t]*acc[3][t] + wb[1][t]*acc[2][t]
                + wb[2][t]*acc[1][t] + wb[3][t]*acc[0][t];
        ob[t*HW] = 0.25f * r;
        atomicAdd(om + t*HW, 0.03125f * r);   // 0.25 * (1/8)
    }
    #undef ISSUE_STAGE
}

extern "C" void kernel_launch(void* const* d_in, const int* in_sizes, int n_in,
                              void* d_out, int out_size)
{
    const float* frames = (const float*)d_in[0];
    const float* core   = (const float*)d_in[1];
    const float* kw     = (const float*)d_in[2];

    float* out   = (float*)d_out;
    float* out_i = out;                    // pred_img_i: (4,8,3,48,48) = 221184
    float* out_m = out + BB*NN*3*HW;       // pred_img:   (4,3,48,48)   =  27648

    cudaFuncSetAttribute(kpn_kernel,
                         cudaFuncAttributeMaxDynamicSharedMemorySize,
                         SMEM_BYTES);

    zero_kernel<<<(OUTM_ELEMS/4 + 255)/256, 256>>>((float4*)out_m);

    dim3 grid(HH/TH, NN, BB);              // 8 x 8 x 4 = 256 blocks, 1 wave
    kpn_kernel<<<grid, BPIX, SMEM_BYTES>>>(frames, core, kw, out_i, out_m);
}

// round 10
// speedup vs baseline: 1.3155x; 1.1388x over previous
#include <cuda_runtime.h>

#define BB 4
#define NN 8
#define HH 48
#define WW 48
#define HW (HH*WW)        /* 2304 */
#define TH 6
#define SMH (TH+6)
#define SMW (SMH*0+54)    /* WW+6 */
#define BPIX (WW*TH)      /* 288 */
#define OUT_I_ELEMS (BB*NN*3*HW)   /* 221184 */
#define OUTM_ELEMS (BB*3*HW)       /* 27648  */
#define ZERO_TOT ((OUT_I_ELEMS + OUTM_ELEMS)/4)   /* 62208 float4 */

// Zero out_i + out_m (both are atomically accumulated).
__global__ void zero_kernel(float4* __restrict__ p)
{
    int i = blockIdx.x * blockDim.x + threadIdx.x;
    if (i < ZERO_TOT) p[i] = make_float4(0.f, 0.f, 0.f, 0.f);
}

// Fully decomposed rank-1 kernel-prediction apply.
// One block = one (tile, color c, RGB t, n, b). It computes the partial
//   r = sum_s W[b,n,s,t] * S^c_{K(s)},  K(s)=7,5,3,1
//   S^c_K = sum_k c1[cur+k,c,t] * sum_l c2[cur+l,c,t] * F[c, h+k-3, w+l-3]
// and accumulates 0.25*r into pred_img_i and r/32 into pred_img via atomics.
// No load/compute phase barriers: 36 LDGs issued up front per thread, 3072
// blocks give ~27 independent warps per SM streaming continuously.
__global__ __launch_bounds__(BPIX, 3)
void kpn_kernel(const float* __restrict__ frames,
                const float* __restrict__ core,
                const float* __restrict__ kw,
                float* __restrict__ out_i,
                float* __restrict__ out_m)
{
    const int gx   = blockIdx.x;        // 8 tiles * 12 (c,t)
    const int tile = gx / 12;
    const int ct   = gx - tile*12;
    const int c    = ct & 3;
    const int t    = ct >> 2;
    const int n    = blockIdx.y;
    const int b    = blockIdx.z;
    const int h0   = tile * TH;

    __shared__ float sF[SMH][SMW];      // one color, 648 floats

    const int tid = threadIdx.x;
    const int w   = tid % WW;
    const int ti  = tid / WW;
    const int pix = h0*WW + tid;        // contiguous: (h0+ti)*48 + w

    // ---- batch ALL global loads up front (36 LDG / thread) ----
    // core channel (within b,n): ch = q*12 + c*3 + t, stride HW
    const float* cbase = core + ((size_t)b*3072 + (size_t)n*384
                                 + (size_t)(c*3 + t)) * HW + pix;
    float c1v[16], c2v[16];
    #pragma unroll
    for (int q = 0; q < 16; q++) {
        c1v[q] = cbase[(size_t)( q      *12) * HW];
        c2v[q] = cbase[(size_t)((16+q)*12) * HW];
    }
    // kernel_weight[b][n][s][t][h][w], s=0 pairs with K=7 (KS[::-1] stack)
    const float* wbp = kw + ((size_t)(b*NN + n))*12*HW + (size_t)t*HW + pix;
    float wb0 = wbp[0], wb1 = wbp[3*HW], wb2 = wbp[6*HW], wb3 = wbp[9*HW];

    // ---- frames tile for color c (zero-padded halo of 3) ----
    const float* fbase = frames + ((size_t)((b*NN + n)*4 + c)) * HW;
    #pragma unroll
    for (int k = 0; k < 3; k++) {       // 648 = 2.25 * 288
        int idx = k*BPIX + tid;
        if (idx < SMH*SMW) {
            int i  = idx / SMW;
            int j  = idx - i*SMW;
            int hh = h0 + i - 3;
            int wp = j - 3;
            float v = 0.f;
            if ((unsigned)hh < HH && (unsigned)wp < WW)
                v = fbase[hh*WW + wp];
            sF[i][j] = v;
        }
    }
    __syncthreads();

    // ---- 7-row walk; row i feeds K7 always, K5 rows 1..5, K3 rows 2..4,
    //      K1 row 3 ----
    float acc0 = 0.f, acc1 = 0.f, acc2 = 0.f, acc3 = 0.f;  // K1,K3,K5,K7
    #pragma unroll
    for (int i = 0; i < 7; i++) {
        float v[7];
        #pragma unroll
        for (int l = 0; l < 7; l++)
            v[l] = sF[ti + i][w + l];

        float rs7 = 0.f;
        #pragma unroll
        for (int l = 0; l < 7; l++)
            rs7 += c2v[9 + l] * v[l];
        acc3 += c1v[9 + i] * rs7;

        if (i >= 1 && i <= 5) {
            float rs5 = 0.f;
            #pragma unroll
            for (int l = 0; l < 5; l++)
                rs5 += c2v[4 + l] * v[1 + l];
            acc2 += c1v[4 + (i - 1)] * rs5;
        }
        if (i >= 2 && i <= 4) {
            float rs3 = c2v[1]*v[2] + c2v[2]*v[3] + c2v[3]*v[4];
            acc1 += c1v[1 + (i - 2)] * rs3;
        }
        if (i == 3)
            acc0 += c1v[0] * (c2v[0] * v[3]);
    }

    float r = wb0*acc3 + wb1*acc2 + wb2*acc1 + wb3*acc0;

    atomicAdd(out_i + ((size_t)(b*NN + n))*3*HW + (size_t)t*HW + pix,
              0.25f * r);
    atomicAdd(out_m + (size_t)b*3*HW + (size_t)t*HW + pix,
              0.03125f * r);              // 0.25 * (1/8)
}

extern "C" void kernel_launch(void* const* d_in, const int* in_sizes, int n_in,
                              void* d_out, int out_size)
{
    const float* frames = (const float*)d_in[0];
    const float* core   = (const float*)d_in[1];
    const float* kw     = (const float*)d_in[2];

    float* out   = (float*)d_out;
    float* out_i = out;                    // pred_img_i: (4,8,3,48,48)
    float* out_m = out + OUT_I_ELEMS;      // pred_img:   (4,3,48,48)

    zero_kernel<<<(ZERO_TOT + 255)/256, 256>>>((float4*)out);

    dim3 grid((HH/TH)*12, NN, BB);         // 96 x 8 x 4 = 3072 blocks
    kpn_kernel<<<grid, BPIX>>>(frames, core, kw, out_i, out_m);
}